// round 4
// baseline (speedup 1.0000x reference)
#include <cuda_runtime.h>
#include <math.h>

#define NSNPS  500000
#define NGENES 20000
#define NNODES 600000
#define NEDGES 320000
#define NB     16
#define NF     8

// rsqrt(1 + 1e-5)
#define BN_RS 0.9999950000374997f

// -------- scratch (static device allocations; no runtime alloc) --------
__device__ float d_snpT[(size_t)NSNPS * NB];     // 32 MB  [snp][b]
__device__ float d_fT[(size_t)NSNPS * NF];       // 16 MB  [snp][f]
__device__ float d_hA[(size_t)NGENES * NB * NF]; // 10.24 MB [g][b][f]
__device__ float d_hB[(size_t)NGENES * NB * NF];
__device__ int   d_seg[NGENES + 1];
__device__ int   d_deg[NGENES];
__device__ int   d_cur[NGENES];
__device__ int   d_off[NGENES + 1];
__device__ int   d_csr[NEDGES];
__device__ float d_gh[NB * NF];

__device__ __forceinline__ float gelu_f(float x) { return x * normcdff(x); }

// -------- zero small scratch --------
__global__ void k_zero() {
    int i = blockIdx.x * blockDim.x + threadIdx.x;
    if (i < NGENES) { d_deg[i] = 0; d_cur[i] = 0; }
    if (i < NB * NF) d_gh[i] = 0.f;
}

// -------- transpose snp -> snpT, filters -> fT, and copy filters to output --------
__global__ void k_pre(const float* __restrict__ snp,
                      const float* __restrict__ filters,
                      float* __restrict__ outF) {
    int t = blockIdx.x * blockDim.x + threadIdx.x;
    if (t >= NSNPS) return;
    float v[NB];
#pragma unroll
    for (int b = 0; b < NB; b++) v[b] = snp[(size_t)b * NSNPS + t];
    float4* dp = (float4*)&d_snpT[(size_t)t * NB];
    dp[0] = make_float4(v[0], v[1], v[2], v[3]);
    dp[1] = make_float4(v[4], v[5], v[6], v[7]);
    dp[2] = make_float4(v[8], v[9], v[10], v[11]);
    dp[3] = make_float4(v[12], v[13], v[14], v[15]);
    float w[NF];
#pragma unroll
    for (int f = 0; f < NF; f++) {
        w[f] = filters[(size_t)f * NSNPS + t];
        outF[(size_t)f * NSNPS + t] = w[f];
    }
    float4* fp = (float4*)&d_fT[(size_t)t * NF];
    fp[0] = make_float4(w[0], w[1], w[2], w[3]);
    fp[1] = make_float4(w[4], w[5], w[6], w[7]);
}

// -------- per-gene node-segment starts (gene_of_node is sorted) --------
__global__ void k_seg(const int* __restrict__ gon) {
    int g = blockIdx.x * blockDim.x + threadIdx.x;
    if (g > NGENES) return;
    int lo = 0, hi = NNODES;
    while (lo < hi) {
        int mid = (lo + hi) >> 1;
        if (gon[mid] < g) lo = mid + 1; else hi = mid;
    }
    d_seg[g] = lo;
}

// -------- CSR build: histogram, scan, scatter --------
__global__ void k_hist(const int* __restrict__ dst) {
    int e = blockIdx.x * blockDim.x + threadIdx.x;
    if (e < NEDGES) atomicAdd(&d_deg[dst[e]], 1);
}

__global__ void k_scan() {
    __shared__ int sh[1024];
    const int PER = (NGENES + 1023) / 1024;  // 20
    int tid = threadIdx.x;
    int base = tid * PER;
    int s = 0;
    for (int i = 0; i < PER; i++) {
        int idx = base + i;
        if (idx < NGENES) s += d_deg[idx];
    }
    sh[tid] = s;
    __syncthreads();
    for (int off = 1; off < 1024; off <<= 1) {
        int add = 0;
        if (tid >= off) add = sh[tid - off];
        __syncthreads();
        sh[tid] += add;
        __syncthreads();
    }
    int run = (tid == 0) ? 0 : sh[tid - 1];
    for (int i = 0; i < PER; i++) {
        int idx = base + i;
        if (idx < NGENES) { d_off[idx] = run; run += d_deg[idx]; }
    }
    if (tid == 1023) d_off[NGENES] = run;
}

__global__ void k_scatter(const int* __restrict__ src, const int* __restrict__ dst) {
    int e = blockIdx.x * blockDim.x + threadIdx.x;
    if (e >= NEDGES) return;
    int d = dst[e];
    int p = atomicAdd(&d_cur[d], 1);
    d_csr[d_off[d] + p] = src[e];
}

// -------- SNP -> gene readout: hA[g][b][f] = sum_{n in seg(g)} snp[b,id]*filters[f,id] --------
__global__ void k_gene(const int* __restrict__ snp_ids) {
    int tid = threadIdx.x;
    int g = blockIdx.x * 16 + (tid >> 4);
    int b = tid & 15;
    if (g >= NGENES) return;
    float4 a0 = make_float4(0.f, 0.f, 0.f, 0.f);
    float4 a1 = a0;
    int n0 = d_seg[g], n1 = d_seg[g + 1];
    for (int n = n0; n < n1; n++) {
        int id = snp_ids[n];
        float sv = d_snpT[(size_t)id * NB + b];
        const float4* fp = (const float4*)&d_fT[(size_t)id * NF];
        float4 f0 = fp[0], f1 = fp[1];
        a0.x += sv * f0.x; a0.y += sv * f0.y; a0.z += sv * f0.z; a0.w += sv * f0.w;
        a1.x += sv * f1.x; a1.y += sv * f1.y; a1.z += sv * f1.z; a1.w += sv * f1.w;
    }
    float4* hp = (float4*)&d_hA[((size_t)g * NB + b) * NF];
    hp[0] = a0; hp[1] = a1;
}

// -------- one GIN layer: edge agg (CSR gather) + MLP(8->16->8) + BN + GELU, fused --------
__global__ void k_layer(int l,
                        const float* __restrict__ eps,
                        const float* __restrict__ W1, const float* __restrict__ b1,
                        const float* __restrict__ g1, const float* __restrict__ bt1,
                        const float* __restrict__ W2, const float* __restrict__ b2,
                        const float* __restrict__ g2, const float* __restrict__ bt2) {
    __shared__ float sW1[128], sW2[128], sB1[16], sG1[16], sT1[16], sB2[8], sG2[8], sT2[8];
    int tid = threadIdx.x;
    if (tid < 128) { sW1[tid] = W1[l * 128 + tid]; sW2[tid] = W2[l * 128 + tid]; }
    if (tid < 16) {
        sB1[tid] = b1[l * 16 + tid];
        sG1[tid] = g1[l * 16 + tid] * BN_RS;
        sT1[tid] = bt1[l * 16 + tid];
    }
    if (tid < 8) {
        sB2[tid] = b2[l * 8 + tid];
        sG2[tid] = g2[l * 8 + tid] * BN_RS;
        sT2[tid] = bt2[l * 8 + tid];
    }
    __syncthreads();

    const float* hin = (l == 0) ? d_hA : d_hB;
    float* hout      = (l == 0) ? d_hB : d_hA;

    int g = blockIdx.x * 16 + (tid >> 4);
    int b = tid & 15;
    if (g >= NGENES) return;

    float ep = 1.f + eps[l];
    const float4* hp = (const float4*)&hin[((size_t)g * NB + b) * NF];
    float4 a0 = hp[0], a1 = hp[1];
    a0.x *= ep; a0.y *= ep; a0.z *= ep; a0.w *= ep;
    a1.x *= ep; a1.y *= ep; a1.z *= ep; a1.w *= ep;

    int e0 = d_off[g], e1 = d_off[g + 1];
    for (int e = e0; e < e1; e++) {
        int s = d_csr[e];
        const float4* sp = (const float4*)&hin[((size_t)s * NB + b) * NF];
        float4 x0 = sp[0], x1 = sp[1];
        a0.x += x0.x; a0.y += x0.y; a0.z += x0.z; a0.w += x0.w;
        a1.x += x1.x; a1.y += x1.y; a1.z += x1.z; a1.w += x1.w;
    }
    float acc[8] = {a0.x, a0.y, a0.z, a0.w, a1.x, a1.y, a1.z, a1.w};

    float h2[16];
#pragma unroll
    for (int j = 0; j < 16; j++) {
        float t = sB1[j];
#pragma unroll
        for (int f = 0; f < 8; f++) t += acc[f] * sW1[f * 16 + j];
        h2[j] = gelu_f(t * sG1[j] + sT1[j]);
    }
    float o[8];
#pragma unroll
    for (int f = 0; f < 8; f++) {
        float t = sB2[f];
#pragma unroll
        for (int j = 0; j < 16; j++) t += h2[j] * sW2[j * 8 + f];
        o[f] = gelu_f(t * sG2[f] + sT2[f]);
    }
    float4* op = (float4*)&hout[((size_t)g * NB + b) * NF];
    op[0] = make_float4(o[0], o[1], o[2], o[3]);
    op[1] = make_float4(o[4], o[5], o[6], o[7]);
}

// -------- attentive readout: w = sigmoid(Wq(key(h))), gh[b] = sum_g value(h)*w --------
__global__ void k_attn(const float* __restrict__ Wk, const float* __restrict__ bk,
                       const float* __restrict__ Wq,
                       const float* __restrict__ Wv, const float* __restrict__ bv,
                       float* __restrict__ w_out) {
    int b = blockIdx.y;
    int g = blockIdx.x * blockDim.x + threadIdx.x;
    const float* h = d_hA;  // after L=2 layers, result lives in hA
    float vw[8] = {0.f, 0.f, 0.f, 0.f, 0.f, 0.f, 0.f, 0.f};
    if (g < NGENES) {
        const float* hp = &h[((size_t)g * NB + b) * NF];
        float x[8];
#pragma unroll
        for (int f = 0; f < 8; f++) x[f] = hp[f];
        float q = 0.f;
#pragma unroll
        for (int j = 0; j < 8; j++) {
            float key = bk[j];
#pragma unroll
            for (int f = 0; f < 8; f++) key += x[f] * Wk[f * 8 + j];
            q += key * Wq[j];
        }
        float wv = 1.f / (1.f + expf(-q));
        w_out[(size_t)b * NGENES + g] = wv;
#pragma unroll
        for (int j = 0; j < 8; j++) {
            float v = bv[j];
#pragma unroll
            for (int f = 0; f < 8; f++) v += x[f] * Wv[f * 8 + j];
            vw[j] = v * wv;
        }
    }
#pragma unroll
    for (int off = 16; off > 0; off >>= 1)
#pragma unroll
        for (int j = 0; j < 8; j++) vw[j] += __shfl_down_sync(0xffffffffu, vw[j], off);
    __shared__ float red[8][8];
    int wid = threadIdx.x >> 5, lane = threadIdx.x & 31;
    if (lane == 0)
        for (int j = 0; j < 8; j++) red[wid][j] = vw[j];
    __syncthreads();
    if (threadIdx.x < 8) {
        float s = 0.f;
        for (int w = 0; w < 8; w++) s += red[w][threadIdx.x];
        atomicAdd(&d_gh[b * NF + threadIdx.x], s);
    }
}

// -------- final MLP head: 8 -> 64 -> 16 -> 1 --------
__global__ void k_head(const float* __restrict__ Wp1, const float* __restrict__ bp1,
                       const float* __restrict__ gp1, const float* __restrict__ btp1,
                       const float* __restrict__ Wp2, const float* __restrict__ bp2,
                       const float* __restrict__ gp2, const float* __restrict__ btp2,
                       const float* __restrict__ Wp3, const float* __restrict__ bp3,
                       float* __restrict__ preds) {
    int b = threadIdx.x;
    if (b >= NB) return;
    float x[8];
#pragma unroll
    for (int f = 0; f < 8; f++) x[f] = d_gh[b * 8 + f];
    float z1[64];
    for (int j = 0; j < 64; j++) {
        float t = bp1[j];
#pragma unroll
        for (int f = 0; f < 8; f++) t += x[f] * Wp1[f * 64 + j];
        z1[j] = gelu_f(t * BN_RS * gp1[j] + btp1[j]);
    }
    float z2[16];
    for (int k = 0; k < 16; k++) {
        float t = bp2[k];
        for (int j = 0; j < 64; j++) t += z1[j] * Wp2[j * 16 + k];
        z2[k] = gelu_f(t * BN_RS * gp2[k] + btp2[k]);
    }
    float p = bp3[0];
#pragma unroll
    for (int k = 0; k < 16; k++) p += z2[k] * Wp3[k];
    preds[b] = p;
}

extern "C" void kernel_launch(void* const* d_in, const int* in_sizes, int n_in,
                              void* d_out, int out_size) {
    const float* snp     = (const float*)d_in[0];
    const int*   snp_ids = (const int*)d_in[1];
    const int*   gon     = (const int*)d_in[2];
    const int*   esrc    = (const int*)d_in[3];
    const int*   edst    = (const int*)d_in[4];
    const float* filters = (const float*)d_in[5];
    const float* eps     = (const float*)d_in[6];
    const float* W1  = (const float*)d_in[7];
    const float* b1  = (const float*)d_in[8];
    const float* g1  = (const float*)d_in[9];
    const float* bt1 = (const float*)d_in[10];
    const float* W2  = (const float*)d_in[11];
    const float* b2  = (const float*)d_in[12];
    const float* g2  = (const float*)d_in[13];
    const float* bt2 = (const float*)d_in[14];
    const float* Wk  = (const float*)d_in[15];
    const float* bk  = (const float*)d_in[16];
    const float* Wq  = (const float*)d_in[17];
    const float* Wv  = (const float*)d_in[18];
    const float* bv  = (const float*)d_in[19];
    const float* Wp1 = (const float*)d_in[20];
    const float* bp1 = (const float*)d_in[21];
    const float* gp1 = (const float*)d_in[22];
    const float* btp1= (const float*)d_in[23];
    const float* Wp2 = (const float*)d_in[24];
    const float* bp2 = (const float*)d_in[25];
    const float* gp2 = (const float*)d_in[26];
    const float* btp2= (const float*)d_in[27];
    const float* Wp3 = (const float*)d_in[28];
    const float* bp3 = (const float*)d_in[29];

    float* out   = (float*)d_out;
    float* preds = out;                               // [16]
    float* outF  = out + NB;                          // [8*500000]
    float* w_out = out + NB + (size_t)NF * NSNPS;     // [16*20000]

    k_zero<<<(NGENES + 255) / 256, 256>>>();
    k_pre<<<(NSNPS + 255) / 256, 256>>>(snp, filters, outF);
    k_seg<<<(NGENES + 1 + 255) / 256, 256>>>(gon);
    k_hist<<<(NEDGES + 255) / 256, 256>>>(edst);
    k_scan<<<1, 1024>>>();
    k_scatter<<<(NEDGES + 255) / 256, 256>>>(esrc, edst);
    k_gene<<<NGENES / 16, 256>>>(snp_ids);
    k_layer<<<NGENES / 16, 256>>>(0, eps, W1, b1, g1, bt1, W2, b2, g2, bt2);
    k_layer<<<NGENES / 16, 256>>>(1, eps, W1, b1, g1, bt1, W2, b2, g2, bt2);
    {
        dim3 grid((NGENES + 255) / 256, NB);
        k_attn<<<grid, 256>>>(Wk, bk, Wq, Wv, bv, w_out);
    }
    k_head<<<1, 32>>>(Wp1, bp1, gp1, btp1, Wp2, bp2, gp2, btp2, Wp3, bp3, preds);
}